// round 4
// baseline (speedup 1.0000x reference)
#include <cuda_runtime.h>
#include <cuda_bf16.h>
#include <cstdint>

// ---------------------------------------------------------------------------
// Problem sizes (fixed)
// ---------------------------------------------------------------------------
#define BB 8
#define QQ 128
#define VV 512
#define HH 512

#define NQ (BB*QQ*HH)   // 524288
#define NV (BB*VV*HH)   // 2097152
#define NW (HH*HH)      // 262144

// ---------------------------------------------------------------------------
// Device scratch (no allocations allowed)
// ---------------------------------------------------------------------------
__device__ __nv_bfloat16 g_qhi[NQ], g_qlo[NQ];
__device__ __nv_bfloat16 g_vhi[NV], g_vlo[NV];
__device__ __nv_bfloat16 g_wqhi[NW], g_wqlo[NW];
__device__ __nv_bfloat16 g_wvhi[NW], g_wvlo[NW];
__device__ float g_qp[NQ];
__device__ float g_vp[NV];

// ---------------------------------------------------------------------------
// Fast transcendentals
// ---------------------------------------------------------------------------
__device__ __forceinline__ float fast_ex2(float x) {
    float y;
    asm("ex2.approx.ftz.f32 %0, %1;" : "=f"(y) : "f"(x));
    return y;
}
__device__ __forceinline__ float tanh_fast(float x) {
    float y;
    asm("tanh.approx.f32 %0, %1;" : "=f"(y) : "f"(x));
    return y;
}

// cp.async helpers
__device__ __forceinline__ void cp_async16(float* dst_smem, const float* src_gmem) {
    uint32_t d = (uint32_t)__cvta_generic_to_shared(dst_smem);
    asm volatile("cp.async.cg.shared.global [%0], [%1], 16;\n" :: "r"(d), "l"(src_gmem) : "memory");
}
__device__ __forceinline__ void cp_commit() {
    asm volatile("cp.async.commit_group;\n" ::: "memory");
}
__device__ __forceinline__ void cp_wait1() {
    asm volatile("cp.async.wait_group 1;\n" ::: "memory");
}
__device__ __forceinline__ void cp_wait0() {
    asm volatile("cp.async.wait_group 0;\n" ::: "memory");
}

// ---------------------------------------------------------------------------
// K1: fused split fp32 -> bf16 hi + bf16 lo for all four tensors
// ---------------------------------------------------------------------------
__global__ void convert_all_kernel(const float* __restrict__ query,
                                   const float* __restrict__ values,
                                   const float* __restrict__ Wq,
                                   const float* __restrict__ Wv,
                                   __nv_bfloat16* __restrict__ qhi, __nv_bfloat16* __restrict__ qlo,
                                   __nv_bfloat16* __restrict__ vhi, __nv_bfloat16* __restrict__ vlo,
                                   __nv_bfloat16* __restrict__ wqhi, __nv_bfloat16* __restrict__ wqlo,
                                   __nv_bfloat16* __restrict__ wvhi, __nv_bfloat16* __restrict__ wvlo) {
    int i = blockIdx.x * blockDim.x + threadIdx.x;
    const float* src;
    __nv_bfloat16 *hi, *lo;
    int j = i;
    if (j < NQ)                    { src = query;  hi = qhi;  lo = qlo;  }
    else if ((j -= NQ) < NV)       { src = values; hi = vhi;  lo = vlo;  }
    else if ((j -= NV) < NW)       { src = Wq;     hi = wqhi; lo = wqlo; }
    else if ((j -= NW) < NW)       { src = Wv;     hi = wvhi; lo = wvlo; }
    else return;
    float x = src[j];
    __nv_bfloat16 h = __float2bfloat16(x);
    hi[j] = h;
    lo[j] = __float2bfloat16(x - __bfloat162float(h));
}

// ---------------------------------------------------------------------------
// K2: C[m][n] = sum_k A[m][k]*B[n][k] + bias[n]   (NT GEMM, 3x bf16 split)
// ---------------------------------------------------------------------------
#define GBM 128
#define GBN 64
#define GBK 32

__device__ __forceinline__ void mma16816(float* d, const uint32_t* a, const uint32_t* b) {
    asm volatile(
        "mma.sync.aligned.m16n8k16.row.col.f32.bf16.bf16.f32 "
        "{%0,%1,%2,%3}, {%4,%5,%6,%7}, {%8,%9}, {%0,%1,%2,%3};"
        : "+f"(d[0]), "+f"(d[1]), "+f"(d[2]), "+f"(d[3])
        : "r"(a[0]), "r"(a[1]), "r"(a[2]), "r"(a[3]), "r"(b[0]), "r"(b[1]));
}

__global__ __launch_bounds__(256) void gemm_nt_split_kernel(
    const __nv_bfloat16* __restrict__ Ahi, const __nv_bfloat16* __restrict__ Alo,
    const __nv_bfloat16* __restrict__ Bhi, const __nv_bfloat16* __restrict__ Blo,
    const float* __restrict__ bias, float* __restrict__ C) {
    const int K = HH;
    const int N = HH;
    __shared__ __align__(16) __nv_bfloat16 As[2][GBM][GBK + 8];
    __shared__ __align__(16) __nv_bfloat16 Bs[2][GBN][GBK + 8];

    const int m0 = blockIdx.x * GBM;
    const int n0 = blockIdx.y * GBN;
    const int tid = threadIdx.x;
    const int wid = tid >> 5;
    const int lane = tid & 31;
    const int wm = (wid >> 1) * 32;
    const int wn = (wid & 1) * 32;
    const int gp = lane >> 2;
    const int tg = lane & 3;

    float d[2][4][4];
#pragma unroll
    for (int mi = 0; mi < 2; mi++)
#pragma unroll
        for (int ni = 0; ni < 4; ni++)
#pragma unroll
            for (int r = 0; r < 4; r++) d[mi][ni][r] = 0.0f;

    for (int k0 = 0; k0 < K; k0 += GBK) {
        __syncthreads();
#pragma unroll
        for (int s = 0; s < 2; s++) {
            const __nv_bfloat16* srcA = s ? Alo : Ahi;
#pragma unroll
            for (int i = 0; i < 2; i++) {
                int linear = i * 256 + tid;
                int r = linear >> 2;
                int c = (linear & 3) * 8;
                uint4 v = *(const uint4*)(srcA + (size_t)(m0 + r) * K + k0 + c);
                *(uint4*)(&As[s][r][c]) = v;
            }
            const __nv_bfloat16* srcB = s ? Blo : Bhi;
            {
                int r = tid >> 2;
                int c = (tid & 3) * 8;
                uint4 v = *(const uint4*)(srcB + (size_t)(n0 + r) * K + k0 + c);
                *(uint4*)(&Bs[s][r][c]) = v;
            }
        }
        __syncthreads();

#pragma unroll
        for (int ks = 0; ks < GBK; ks += 16) {
            uint32_t a[2][2][4];
            uint32_t bf[2][4][2];
#pragma unroll
            for (int s = 0; s < 2; s++) {
#pragma unroll
                for (int mi = 0; mi < 2; mi++) {
                    int row = wm + mi * 16;
                    a[s][mi][0] = *(const uint32_t*)&As[s][row + gp][ks + tg * 2];
                    a[s][mi][1] = *(const uint32_t*)&As[s][row + gp + 8][ks + tg * 2];
                    a[s][mi][2] = *(const uint32_t*)&As[s][row + gp][ks + tg * 2 + 8];
                    a[s][mi][3] = *(const uint32_t*)&As[s][row + gp + 8][ks + tg * 2 + 8];
                }
#pragma unroll
                for (int ni = 0; ni < 4; ni++) {
                    int col = wn + ni * 8;
                    bf[s][ni][0] = *(const uint32_t*)&Bs[s][col + gp][ks + tg * 2];
                    bf[s][ni][1] = *(const uint32_t*)&Bs[s][col + gp][ks + tg * 2 + 8];
                }
            }
#pragma unroll
            for (int mi = 0; mi < 2; mi++)
#pragma unroll
                for (int ni = 0; ni < 4; ni++) {
                    mma16816(d[mi][ni], a[0][mi], bf[0][ni]);  // hi*hi
                    mma16816(d[mi][ni], a[0][mi], bf[1][ni]);  // hi*lo
                    mma16816(d[mi][ni], a[1][mi], bf[0][ni]);  // lo*hi
                }
        }
    }

#pragma unroll
    for (int mi = 0; mi < 2; mi++)
#pragma unroll
        for (int ni = 0; ni < 4; ni++) {
            int r = m0 + wm + mi * 16 + gp;
            int c = n0 + wn + ni * 8 + tg * 2;
            float b0 = bias[c], b1 = bias[c + 1];
            float* Cp = C + (size_t)r * N + c;
            float2 v0 = make_float2(d[mi][ni][0] + b0, d[mi][ni][1] + b1);
            float2 v1 = make_float2(d[mi][ni][2] + b0, d[mi][ni][3] + b1);
            *(float2*)(Cp) = v0;
            *(float2*)(Cp + 8 * N) = v1;
        }
}

// ---------------------------------------------------------------------------
// K3: fused scores(tanh) + softmax + context, cp.async double-buffered tiles.
// Grid: 128 blocks = (b, 8-query tile). 512 threads.
// VT=32, 16 tiles per phase, 2 smem buffers, prefetch depth 1.
// Score mapping (conflict-free, hc = lane bits 3-4):
//   q = tid>>6, s6 = tid&63, hc = (s6>>3)&3 (contiguous 128-float H quarter),
//   rgrp = (s6&7)|((s6&32)>>2) in 0..15; thread handles rows rgrp, rgrp+16.
//   Per LDS phase the 8 lanes hold 8 consecutive rows (row stride = 129 16B
//   slots == 1 mod 8) -> conflict-free; q/wc loads are warp-broadcast.
// ---------------------------------------------------------------------------
#define QT 8
#define VT 32
#define NTILE (VV/VT)   // 16
#define HP (HH + 4)     // 516 floats; 129 16B slots == 1 mod 8
#define VP (VV + 8)

#define SMEM_FLOATS (QT*HP + HH + QT*VP + 16 + VV + 2*VT*HP)
#define SMEM_BYTES (SMEM_FLOATS * 4)

// stage one VT x 512 tile: 4096 16B chunks, 8 per thread
__device__ __forceinline__ void load_tile_async(float* dst, const float* src, int tid) {
#pragma unroll
    for (int i = 0; i < (VT * 128) / 512; i++) {
        int linear = i * 512 + tid;
        int r = linear >> 7;          // 128 chunks per row
        int c = (linear & 127) << 2;  // float offset
        cp_async16(dst + r * HP + c, src + r * HH + c);
    }
}

__global__ __launch_bounds__(512, 1) void attn_kernel(
    const float* __restrict__ qp, const float* __restrict__ vp,
    const float* __restrict__ values, const int* __restrict__ mask,
    const float* __restrict__ wc, const float* __restrict__ bc,
    float* __restrict__ out_ctx, float* __restrict__ out_w) {
    extern __shared__ float sm[];
    float* qp_s = sm;                    // QT*HP
    float* wc_s = qp_s + QT * HP;        // HH
    float* sc   = wc_s + HH;             // QT*VP
    float* wsum = sc + QT * VP;          // 16
    int* mask_s = (int*)(wsum + 16);     // VV
    float* buf  = (float*)(mask_s + VV); // 2 * VT*HP

    const int tid = threadIdx.x;
    const int b = blockIdx.x >> 4;
    const int qt = blockIdx.x & 15;
    const int q0 = qt * QT;

    const float* vpb = vp + (size_t)b * VV * HH;
    const float* valb = values + (size_t)b * VV * HH;

    // prefetch score tile 0
    load_tile_async(buf, vpb, tid);
    cp_commit();

    // load qp tile, wc, mask (regular loads, overlapped with the cp.async)
    for (int i = tid; i < QT * (HH / 4); i += 512) {
        int r = i / (HH / 4), c = i % (HH / 4);
        ((float4*)(qp_s + r * HP))[c] =
            ((const float4*)(qp + (size_t)(b * QQ + q0 + r) * HH))[c];
    }
    for (int i = tid; i < HH; i += 512) wc_s[i] = wc[i];
    for (int i = tid; i < VV; i += 512) mask_s[i] = mask[b * VV + i];
    const float bcv = bc[0];

    const int q = tid >> 6;                        // 0..7
    const int s6 = tid & 63;
    const int hc = (s6 >> 3) & 3;                  // H quarter (lane bits 3-4)
    const int rgrp = (s6 & 7) | ((s6 & 32) >> 2);  // 0..15

    // ---- score phase (double-buffered) ----
    for (int t = 0; t < NTILE; t++) {
        float* cur = buf + (t & 1) * VT * HP;
        if (t + 1 < NTILE) {
            load_tile_async(buf + ((t + 1) & 1) * VT * HP, vpb + (size_t)(t + 1) * VT * HH, tid);
            cp_commit();
            cp_wait1();
        } else {
            cp_wait0();
        }
        __syncthreads();

        const float* qrow = qp_s + q * HP + hc * 128;
        const float* wrow = wc_s + hc * 128;
        const float* v0p = cur + rgrp * HP + hc * 128;
        const float* v1p = cur + (rgrp + 16) * HP + hc * 128;
        float acc0 = 0.f, acc1 = 0.f;
#pragma unroll 8
        for (int i = 0; i < 32; i++) {
            int h = i * 4;
            float4 a = *(const float4*)(qrow + h);
            float4 w = *(const float4*)(wrow + h);
            float4 c0 = *(const float4*)(v0p + h);
            float4 c1 = *(const float4*)(v1p + h);
            acc0 = fmaf(w.x, tanh_fast(a.x + c0.x), acc0);
            acc0 = fmaf(w.y, tanh_fast(a.y + c0.y), acc0);
            acc0 = fmaf(w.z, tanh_fast(a.z + c0.z), acc0);
            acc0 = fmaf(w.w, tanh_fast(a.w + c0.w), acc0);
            acc1 = fmaf(w.x, tanh_fast(a.x + c1.x), acc1);
            acc1 = fmaf(w.y, tanh_fast(a.y + c1.y), acc1);
            acc1 = fmaf(w.z, tanh_fast(a.z + c1.z), acc1);
            acc1 = fmaf(w.w, tanh_fast(a.w + c1.w), acc1);
        }
        // reduce across the 4 hc lanes (lane bits 3-4)
        acc0 += __shfl_xor_sync(0xffffffffu, acc0, 8);
        acc0 += __shfl_xor_sync(0xffffffffu, acc0, 16);
        acc1 += __shfl_xor_sync(0xffffffffu, acc1, 8);
        acc1 += __shfl_xor_sync(0xffffffffu, acc1, 16);
        // lanes hc==0 / hc==1 write the two rows
        if (hc < 2) {
            float myacc = (hc == 0) ? acc0 : acc1;
            int v = t * VT + rgrp + 16 * hc;
            float p = mask_s[v] ? fast_ex2((myacc + bcv) * 1.4426950408889634f) : 0.0f;
            sc[q * VP + v] = p;
        }
        __syncthreads();
    }

    // prefetch first values tile while doing softmax
    load_tile_async(buf, valb, tid);
    cp_commit();

    // ---- deterministic row sums ----
    const int vl = tid & 63;
    {
        float s = 0.0f;
#pragma unroll
        for (int j = 0; j < 8; j++) s += sc[q * VP + vl + 64 * j];
#pragma unroll
        for (int off = 16; off; off >>= 1) s += __shfl_down_sync(0xffffffffu, s, off);
        if ((tid & 31) == 0) wsum[tid >> 5] = s;
    }
    __syncthreads();
    const float inv = 1.0f / (wsum[2 * q] + wsum[2 * q + 1]);

    // normalize in smem + write weights output
    {
        float* outw_row = out_w + (size_t)(b * QQ + q0 + q) * VV;
#pragma unroll
        for (int j = 0; j < 8; j++) {
            int v = vl + 64 * j;
            float w = sc[q * VP + v] * inv;
            sc[q * VP + v] = w;
            outw_row[v] = w;
        }
    }

    // ---- context phase (double-buffered): ctx[q][h] = sum_v w[q][v]*values[v][h]
    const int hq = tid & 127;  // float4 column 0..127
    const int qg = tid >> 7;   // 0..3 -> queries 2qg, 2qg+1
    float4 acc0 = make_float4(0.f, 0.f, 0.f, 0.f);
    float4 acc1 = make_float4(0.f, 0.f, 0.f, 0.f);

    for (int t = 0; t < NTILE; t++) {
        float* cur = buf + (t & 1) * VT * HP;
        if (t + 1 < NTILE) {
            load_tile_async(buf + ((t + 1) & 1) * VT * HP, valb + (size_t)(t + 1) * VT * HH, tid);
            cp_commit();
            cp_wait1();
        } else {
            cp_wait0();
        }
        __syncthreads();

        const float* w0 = sc + (2 * qg) * VP + t * VT;
        const float* w1 = sc + (2 * qg + 1) * VP + t * VT;
#pragma unroll 4
        for (int v = 0; v < VT; v += 2) {
            float2 a0 = *(const float2*)(w0 + v);
            float2 a1 = *(const float2*)(w1 + v);
            float4 c0 = ((const float4*)(cur + v * HP))[hq];
            float4 c1 = ((const float4*)(cur + (v + 1) * HP))[hq];
            acc0.x += a0.x * c0.x + a0.y * c1.x;
            acc0.y += a0.x * c0.y + a0.y * c1.y;
            acc0.z += a0.x * c0.z + a0.y * c1.z;
            acc0.w += a0.x * c0.w + a0.y * c1.w;
            acc1.x += a1.x * c0.x + a1.y * c1.x;
            acc1.y += a1.x * c0.y + a1.y * c1.y;
            acc1.z += a1.x * c0.z + a1.y * c1.z;
            acc1.w += a1.x * c0.w + a1.y * c1.w;
        }
        __syncthreads();
    }
    float* oc0 = out_ctx + (size_t)(b * QQ + q0 + 2 * qg) * HH;
    ((float4*)oc0)[hq] = acc0;
    ((float4*)(oc0 + HH))[hq] = acc1;
}

// ---------------------------------------------------------------------------
// Launch
// ---------------------------------------------------------------------------
extern "C" void kernel_launch(void* const* d_in, const int* in_sizes, int n_in,
                              void* d_out, int out_size) {
    const float* query  = (const float*)d_in[0];
    const float* values = (const float*)d_in[1];
    const int*   mask   = (const int*)d_in[2];
    const float* Wq     = (const float*)d_in[3];
    const float* bq     = (const float*)d_in[4];
    const float* Wv     = (const float*)d_in[5];
    const float* bv     = (const float*)d_in[6];
    const float* wc     = (const float*)d_in[7];
    const float* bc     = (const float*)d_in[8];

    float* out_ctx = (float*)d_out;
    float* out_w   = (float*)d_out + (size_t)BB * QQ * HH;

    void *qhi, *qlo, *vhi, *vlo, *wqhi, *wqlo, *wvhi, *wvlo, *qp, *vp;
    cudaGetSymbolAddress(&qhi, g_qhi);
    cudaGetSymbolAddress(&qlo, g_qlo);
    cudaGetSymbolAddress(&vhi, g_vhi);
    cudaGetSymbolAddress(&vlo, g_vlo);
    cudaGetSymbolAddress(&wqhi, g_wqhi);
    cudaGetSymbolAddress(&wqlo, g_wqlo);
    cudaGetSymbolAddress(&wvhi, g_wvhi);
    cudaGetSymbolAddress(&wvlo, g_wvlo);
    cudaGetSymbolAddress(&qp, g_qp);
    cudaGetSymbolAddress(&vp, g_vp);

    // K1: fused bf16 hi/lo split
    const int ntot = NQ + NV + 2 * NW;
    convert_all_kernel<<<(ntot + 255) / 256, 256>>>(
        query, values, Wq, Wv,
        (__nv_bfloat16*)qhi, (__nv_bfloat16*)qlo,
        (__nv_bfloat16*)vhi, (__nv_bfloat16*)vlo,
        (__nv_bfloat16*)wqhi, (__nv_bfloat16*)wqlo,
        (__nv_bfloat16*)wvhi, (__nv_bfloat16*)wvlo);

    // K2: projections
    dim3 gq(BB * QQ / GBM, HH / GBN);   // (8, 8)
    dim3 gv(BB * VV / GBM, HH / GBN);   // (32, 8)
    gemm_nt_split_kernel<<<gq, 256>>>((__nv_bfloat16*)qhi, (__nv_bfloat16*)qlo,
                                      (__nv_bfloat16*)wqhi, (__nv_bfloat16*)wqlo,
                                      bq, (float*)qp);
    gemm_nt_split_kernel<<<gv, 256>>>((__nv_bfloat16*)vhi, (__nv_bfloat16*)vlo,
                                      (__nv_bfloat16*)wvhi, (__nv_bfloat16*)wvlo,
                                      bv, (float*)vp);

    // K3: fused tanh-scores + softmax + context (pipelined)
    cudaFuncSetAttribute(attn_kernel, cudaFuncAttributeMaxDynamicSharedMemorySize, SMEM_BYTES);
    attn_kernel<<<BB * (QQ / QT), 512, SMEM_BYTES>>>(
        (const float*)qp, (const float*)vp, values, mask, wc, bc, out_ctx, out_w);
}

// round 5
// speedup vs baseline: 1.1074x; 1.1074x over previous
#include <cuda_runtime.h>
#include <cuda_bf16.h>
#include <cstdint>

// ---------------------------------------------------------------------------
// Problem sizes (fixed)
// ---------------------------------------------------------------------------
#define BB 8
#define QQ 128
#define VV 512
#define HH 512

#define NQ (BB*QQ*HH)
#define NV (BB*VV*HH)

// ---------------------------------------------------------------------------
// Device scratch (no allocations allowed)
// ---------------------------------------------------------------------------
__device__ float g_qp[NQ];
__device__ float g_vp[NV];

// ---------------------------------------------------------------------------
// Fast transcendentals
// ---------------------------------------------------------------------------
__device__ __forceinline__ float fast_ex2(float x) {
    float y;
    asm("ex2.approx.ftz.f32 %0, %1;" : "=f"(y) : "f"(x));
    return y;
}
__device__ __forceinline__ float tanh_fast(float x) {
    float y;
    asm("tanh.approx.f32 %0, %1;" : "=f"(y) : "f"(x));
    return y;
}

// cp.async helpers
__device__ __forceinline__ void cp_async16(float* dst_smem, const float* src_gmem) {
    uint32_t d = (uint32_t)__cvta_generic_to_shared(dst_smem);
    asm volatile("cp.async.cg.shared.global [%0], [%1], 16;\n" :: "r"(d), "l"(src_gmem) : "memory");
}
__device__ __forceinline__ void cp_commit() {
    asm volatile("cp.async.commit_group;\n" ::: "memory");
}
__device__ __forceinline__ void cp_wait1() {
    asm volatile("cp.async.wait_group 1;\n" ::: "memory");
}
__device__ __forceinline__ void cp_wait0() {
    asm volatile("cp.async.wait_group 0;\n" ::: "memory");
}

// ---------------------------------------------------------------------------
// K2: C[m][n] = sum_k A[m][k]*B[n][k] + bias[n]   (NT GEMM, 3x bf16 split)
// fp32 inputs; hi/lo split happens during smem staging (no convert kernel).
// Block tile 128x64, BK=32, 8 warps (4x2), warp tile 32x32 via m16n8k16.
// ---------------------------------------------------------------------------
#define GBM 128
#define GBN 64
#define GBK 32

__device__ __forceinline__ void mma16816(float* d, const uint32_t* a, const uint32_t* b) {
    asm volatile(
        "mma.sync.aligned.m16n8k16.row.col.f32.bf16.bf16.f32 "
        "{%0,%1,%2,%3}, {%4,%5,%6,%7}, {%8,%9}, {%0,%1,%2,%3};"
        : "+f"(d[0]), "+f"(d[1]), "+f"(d[2]), "+f"(d[3])
        : "r"(a[0]), "r"(a[1]), "r"(a[2]), "r"(a[3]), "r"(b[0]), "r"(b[1]));
}

// split a float4 into 4 hi bf16 (8B) and 4 lo bf16 (8B)
__device__ __forceinline__ void split4(float4 v, uint2* hi, uint2* lo) {
    __nv_bfloat16 h0 = __float2bfloat16(v.x);
    __nv_bfloat16 h1 = __float2bfloat16(v.y);
    __nv_bfloat16 h2 = __float2bfloat16(v.z);
    __nv_bfloat16 h3 = __float2bfloat16(v.w);
    __nv_bfloat16 l0 = __float2bfloat16(v.x - __bfloat162float(h0));
    __nv_bfloat16 l1 = __float2bfloat16(v.y - __bfloat162float(h1));
    __nv_bfloat16 l2 = __float2bfloat16(v.z - __bfloat162float(h2));
    __nv_bfloat16 l3 = __float2bfloat16(v.w - __bfloat162float(h3));
    __nv_bfloat162 hA = {h0, h1}, hB = {h2, h3};
    __nv_bfloat162 lA = {l0, l1}, lB = {l2, l3};
    hi->x = *(uint32_t*)&hA; hi->y = *(uint32_t*)&hB;
    lo->x = *(uint32_t*)&lA; lo->y = *(uint32_t*)&lB;
}

__global__ __launch_bounds__(256) void gemm_nt_split_kernel(
    const float* __restrict__ A, const float* __restrict__ B,
    const float* __restrict__ bias, float* __restrict__ C) {
    const int K = HH;
    const int N = HH;
    __shared__ __align__(16) __nv_bfloat16 As[2][GBM][GBK + 8];
    __shared__ __align__(16) __nv_bfloat16 Bs[2][GBN][GBK + 8];

    const int m0 = blockIdx.x * GBM;
    const int n0 = blockIdx.y * GBN;
    const int tid = threadIdx.x;
    const int wid = tid >> 5;
    const int lane = tid & 31;
    const int wm = (wid >> 1) * 32;
    const int wn = (wid & 1) * 32;
    const int gp = lane >> 2;
    const int tg = lane & 3;

    float d[2][4][4];
#pragma unroll
    for (int mi = 0; mi < 2; mi++)
#pragma unroll
        for (int ni = 0; ni < 4; ni++)
#pragma unroll
            for (int r = 0; r < 4; r++) d[mi][ni][r] = 0.0f;

    for (int k0 = 0; k0 < K; k0 += GBK) {
        __syncthreads();
        // stage A (128x32 fp32 -> hi/lo): 1024 float4 chunks, 4 per thread
#pragma unroll
        for (int i = 0; i < 4; i++) {
            int linear = i * 256 + tid;
            int r = linear >> 3;          // 8 float4 per row
            int c = (linear & 7) * 4;
            float4 v = *(const float4*)(A + (size_t)(m0 + r) * K + k0 + c);
            uint2 hi, lo;
            split4(v, &hi, &lo);
            *(uint2*)(&As[0][r][c]) = hi;
            *(uint2*)(&As[1][r][c]) = lo;
        }
        // stage B (64x32 fp32 -> hi/lo): 512 float4 chunks, 2 per thread
#pragma unroll
        for (int i = 0; i < 2; i++) {
            int linear = i * 256 + tid;
            int r = linear >> 3;
            int c = (linear & 7) * 4;
            float4 v = *(const float4*)(B + (size_t)(n0 + r) * K + k0 + c);
            uint2 hi, lo;
            split4(v, &hi, &lo);
            *(uint2*)(&Bs[0][r][c]) = hi;
            *(uint2*)(&Bs[1][r][c]) = lo;
        }
        __syncthreads();

#pragma unroll
        for (int ks = 0; ks < GBK; ks += 16) {
            uint32_t a[2][2][4];
            uint32_t bf[2][4][2];
#pragma unroll
            for (int s = 0; s < 2; s++) {
#pragma unroll
                for (int mi = 0; mi < 2; mi++) {
                    int row = wm + mi * 16;
                    a[s][mi][0] = *(const uint32_t*)&As[s][row + gp][ks + tg * 2];
                    a[s][mi][1] = *(const uint32_t*)&As[s][row + gp + 8][ks + tg * 2];
                    a[s][mi][2] = *(const uint32_t*)&As[s][row + gp][ks + tg * 2 + 8];
                    a[s][mi][3] = *(const uint32_t*)&As[s][row + gp + 8][ks + tg * 2 + 8];
                }
#pragma unroll
                for (int ni = 0; ni < 4; ni++) {
                    int col = wn + ni * 8;
                    bf[s][ni][0] = *(const uint32_t*)&Bs[s][col + gp][ks + tg * 2];
                    bf[s][ni][1] = *(const uint32_t*)&Bs[s][col + gp][ks + tg * 2 + 8];
                }
            }
#pragma unroll
            for (int mi = 0; mi < 2; mi++)
#pragma unroll
                for (int ni = 0; ni < 4; ni++) {
                    mma16816(d[mi][ni], a[0][mi], bf[0][ni]);  // hi*hi
                    mma16816(d[mi][ni], a[0][mi], bf[1][ni]);  // hi*lo
                    mma16816(d[mi][ni], a[1][mi], bf[0][ni]);  // lo*hi
                }
        }
    }

#pragma unroll
    for (int mi = 0; mi < 2; mi++)
#pragma unroll
        for (int ni = 0; ni < 4; ni++) {
            int r = m0 + wm + mi * 16 + gp;
            int c = n0 + wn + ni * 8 + tg * 2;
            float b0 = bias[c], b1 = bias[c + 1];
            float* Cp = C + (size_t)r * N + c;
            float2 v0 = make_float2(d[mi][ni][0] + b0, d[mi][ni][1] + b1);
            float2 v1 = make_float2(d[mi][ni][2] + b0, d[mi][ni][3] + b1);
            *(float2*)(Cp) = v0;
            *(float2*)(Cp + 8 * N) = v1;
        }
}

// ---------------------------------------------------------------------------
// K3: fused scores(tanh) + softmax + context, cp.async double-buffered tiles.
// Grid: 128 blocks = (b, 8-query tile). 512 threads.
// Score mapping: q = tid>>6 (8), vg = (tid>>3)&7 (8 groups of 4 rows),
// hc = tid&7 (8 interleaved 64-float H chunks, h = i*32 + hc*4).
// 4 v-rows/thread -> 6 B/tanh LDS (85K cyc/SM) < MUFU floor (113K cyc/SM).
// c-load slot = row*129 + i*8 + hc -> 8 lanes distinct mod 8, conflict-free.
// Cross-hc reduction: shfl_xor 1,2,4 (lane bits 0-2); lanes hc<4 write
// rows vg*4 + hc.
// ---------------------------------------------------------------------------
#define QT 8
#define VT 32
#define NTILE (VV/VT)   // 16
#define HP (HH + 4)     // 516 floats; 129 16B slots == 1 mod 8
#define VP (VV + 8)

#define SMEM_FLOATS (QT*HP + HH + QT*VP + 16 + VV + 2*VT*HP)
#define SMEM_BYTES (SMEM_FLOATS * 4)

// stage one VT x 512 tile: 4096 16B chunks, 8 per thread
__device__ __forceinline__ void load_tile_async(float* dst, const float* src, int tid) {
#pragma unroll
    for (int i = 0; i < (VT * 128) / 512; i++) {
        int linear = i * 512 + tid;
        int r = linear >> 7;
        int c = (linear & 127) << 2;
        cp_async16(dst + r * HP + c, src + r * HH + c);
    }
}

__global__ __launch_bounds__(512, 1) void attn_kernel(
    const float* __restrict__ qp, const float* __restrict__ vp,
    const float* __restrict__ values, const int* __restrict__ mask,
    const float* __restrict__ wc, const float* __restrict__ bc,
    float* __restrict__ out_ctx, float* __restrict__ out_w) {
    extern __shared__ float sm[];
    float* qp_s = sm;                    // QT*HP
    float* wc_s = qp_s + QT * HP;        // HH
    float* sc   = wc_s + HH;             // QT*VP
    float* wsum = sc + QT * VP;          // 16
    int* mask_s = (int*)(wsum + 16);     // VV
    float* buf  = (float*)(mask_s + VV); // 2 * VT*HP

    const int tid = threadIdx.x;
    const int b = blockIdx.x >> 4;
    const int qt = blockIdx.x & 15;
    const int q0 = qt * QT;

    const float* vpb = vp + (size_t)b * VV * HH;
    const float* valb = values + (size_t)b * VV * HH;

    // prefetch score tile 0
    load_tile_async(buf, vpb, tid);
    cp_commit();

    // load qp tile, wc, mask (regular loads, overlapped with the cp.async)
    for (int i = tid; i < QT * (HH / 4); i += 512) {
        int r = i / (HH / 4), c = i % (HH / 4);
        ((float4*)(qp_s + r * HP))[c] =
            ((const float4*)(qp + (size_t)(b * QQ + q0 + r) * HH))[c];
    }
    for (int i = tid; i < HH; i += 512) wc_s[i] = wc[i];
    for (int i = tid; i < VV; i += 512) mask_s[i] = mask[b * VV + i];
    const float bcv = bc[0];

    const int q = tid >> 6;          // 0..7
    const int vg = (tid >> 3) & 7;   // 0..7 -> rows vg*4 .. vg*4+3
    const int hc = tid & 7;          // 0..7 interleaved H chunks

    // ---- score phase (double-buffered) ----
    for (int t = 0; t < NTILE; t++) {
        float* cur = buf + (t & 1) * VT * HP;
        if (t + 1 < NTILE) {
            load_tile_async(buf + ((t + 1) & 1) * VT * HP, vpb + (size_t)(t + 1) * VT * HH, tid);
            cp_commit();
            cp_wait1();
        } else {
            cp_wait0();
        }
        __syncthreads();

        const float* qrow = qp_s + q * HP;
        const float* wrow = wc_s;
        const float* v0p = cur + (vg * 4 + 0) * HP;
        const float* v1p = cur + (vg * 4 + 1) * HP;
        const float* v2p = cur + (vg * 4 + 2) * HP;
        const float* v3p = cur + (vg * 4 + 3) * HP;
        float acc0 = 0.f, acc1 = 0.f, acc2 = 0.f, acc3 = 0.f;
#pragma unroll
        for (int i = 0; i < 16; i++) {
            int h = i * 32 + hc * 4;
            float4 a = *(const float4*)(qrow + h);
            float4 w = *(const float4*)(wrow + h);
            float4 c0 = *(const float4*)(v0p + h);
            float4 c1 = *(const float4*)(v1p + h);
            float4 c2 = *(const float4*)(v2p + h);
            float4 c3 = *(const float4*)(v3p + h);
            acc0 = fmaf(w.x, tanh_fast(a.x + c0.x), acc0);
            acc0 = fmaf(w.y, tanh_fast(a.y + c0.y), acc0);
            acc0 = fmaf(w.z, tanh_fast(a.z + c0.z), acc0);
            acc0 = fmaf(w.w, tanh_fast(a.w + c0.w), acc0);
            acc1 = fmaf(w.x, tanh_fast(a.x + c1.x), acc1);
            acc1 = fmaf(w.y, tanh_fast(a.y + c1.y), acc1);
            acc1 = fmaf(w.z, tanh_fast(a.z + c1.z), acc1);
            acc1 = fmaf(w.w, tanh_fast(a.w + c1.w), acc1);
            acc2 = fmaf(w.x, tanh_fast(a.x + c2.x), acc2);
            acc2 = fmaf(w.y, tanh_fast(a.y + c2.y), acc2);
            acc2 = fmaf(w.z, tanh_fast(a.z + c2.z), acc2);
            acc2 = fmaf(w.w, tanh_fast(a.w + c2.w), acc2);
            acc3 = fmaf(w.x, tanh_fast(a.x + c3.x), acc3);
            acc3 = fmaf(w.y, tanh_fast(a.y + c3.y), acc3);
            acc3 = fmaf(w.z, tanh_fast(a.z + c3.z), acc3);
            acc3 = fmaf(w.w, tanh_fast(a.w + c3.w), acc3);
        }
        // reduce across the 8 hc lanes (lane bits 0-2) — deterministic butterfly
        acc0 += __shfl_xor_sync(0xffffffffu, acc0, 1);
        acc0 += __shfl_xor_sync(0xffffffffu, acc0, 2);
        acc0 += __shfl_xor_sync(0xffffffffu, acc0, 4);
        acc1 += __shfl_xor_sync(0xffffffffu, acc1, 1);
        acc1 += __shfl_xor_sync(0xffffffffu, acc1, 2);
        acc1 += __shfl_xor_sync(0xffffffffu, acc1, 4);
        acc2 += __shfl_xor_sync(0xffffffffu, acc2, 1);
        acc2 += __shfl_xor_sync(0xffffffffu, acc2, 2);
        acc2 += __shfl_xor_sync(0xffffffffu, acc2, 4);
        acc3 += __shfl_xor_sync(0xffffffffu, acc3, 1);
        acc3 += __shfl_xor_sync(0xffffffffu, acc3, 2);
        acc3 += __shfl_xor_sync(0xffffffffu, acc3, 4);
        if (hc < 4) {
            float myacc = (hc == 0) ? acc0 : (hc == 1) ? acc1 : (hc == 2) ? acc2 : acc3;
            int v = t * VT + vg * 4 + hc;
            float p = mask_s[v] ? fast_ex2((myacc + bcv) * 1.4426950408889634f) : 0.0f;
            sc[q * VP + v] = p;
        }
        __syncthreads();
    }

    // prefetch first values tile while doing softmax
    load_tile_async(buf, valb, tid);
    cp_commit();

    // ---- deterministic row sums ----
    const int vl = tid & 63;
    {
        float s = 0.0f;
#pragma unroll
        for (int j = 0; j < 8; j++) s += sc[q * VP + vl + 64 * j];
#pragma unroll
        for (int off = 16; off; off >>= 1) s += __shfl_down_sync(0xffffffffu, s, off);
        if ((tid & 31) == 0) wsum[tid >> 5] = s;
    }
    __syncthreads();
    const float inv = 1.0f / (wsum[2 * q] + wsum[2 * q + 1]);

    // normalize in smem + write weights output
    {
        float* outw_row = out_w + (size_t)(b * QQ + q0 + q) * VV;
#pragma unroll
        for (int j = 0; j < 8; j++) {
            int v = vl + 64 * j;
            float w = sc[q * VP + v] * inv;
            sc[q * VP + v] = w;
            outw_row[v] = w;
        }
    }

    // ---- context phase (double-buffered): ctx[q][h] = sum_v w[q][v]*values[v][h]
    const int hq = tid & 127;  // float4 column 0..127
    const int qg = tid >> 7;   // 0..3 -> queries 2qg, 2qg+1
    float4 acc0 = make_float4(0.f, 0.f, 0.f, 0.f);
    float4 acc1 = make_float4(0.f, 0.f, 0.f, 0.f);

    for (int t = 0; t < NTILE; t++) {
        float* cur = buf + (t & 1) * VT * HP;
        if (t + 1 < NTILE) {
            load_tile_async(buf + ((t + 1) & 1) * VT * HP, valb + (size_t)(t + 1) * VT * HH, tid);
            cp_commit();
            cp_wait1();
        } else {
            cp_wait0();
        }
        __syncthreads();

        const float* w0 = sc + (2 * qg) * VP + t * VT;
        const float* w1 = sc + (2 * qg + 1) * VP + t * VT;
#pragma unroll 4
        for (int v = 0; v < VT; v += 2) {
            float2 a0 = *(const float2*)(w0 + v);
            float2 a1 = *(const float2*)(w1 + v);
            float4 c0 = ((const float4*)(cur + v * HP))[hq];
            float4 c1 = ((const float4*)(cur + (v + 1) * HP))[hq];
            acc0.x += a0.x * c0.x + a0.y * c1.x;
            acc0.y += a0.x * c0.y + a0.y * c1.y;
            acc0.z += a0.x * c0.z + a0.y * c1.z;
            acc0.w += a0.x * c0.w + a0.y * c1.w;
            acc1.x += a1.x * c0.x + a1.y * c1.x;
            acc1.y += a1.x * c0.y + a1.y * c1.y;
            acc1.z += a1.x * c0.z + a1.y * c1.z;
            acc1.w += a1.x * c0.w + a1.y * c1.w;
        }
        __syncthreads();
    }
    float* oc0 = out_ctx + (size_t)(b * QQ + q0 + 2 * qg) * HH;
    ((float4*)oc0)[hq] = acc0;
    ((float4*)(oc0 + HH))[hq] = acc1;
}

// ---------------------------------------------------------------------------
// Launch
// ---------------------------------------------------------------------------
extern "C" void kernel_launch(void* const* d_in, const int* in_sizes, int n_in,
                              void* d_out, int out_size) {
    const float* query  = (const float*)d_in[0];
    const float* values = (const float*)d_in[1];
    const int*   mask   = (const int*)d_in[2];
    const float* Wq     = (const float*)d_in[3];
    const float* bq     = (const float*)d_in[4];
    const float* Wv     = (const float*)d_in[5];
    const float* bv     = (const float*)d_in[6];
    const float* wc     = (const float*)d_in[7];
    const float* bc     = (const float*)d_in[8];

    float* out_ctx = (float*)d_out;
    float* out_w   = (float*)d_out + (size_t)BB * QQ * HH;

    void *qp, *vp;
    cudaGetSymbolAddress(&qp, g_qp);
    cudaGetSymbolAddress(&vp, g_vp);

    // K2: projections (fp32 in, split-bf16 tensor GEMM inside)
    dim3 gq(BB * QQ / GBM, HH / GBN);   // (8, 8)
    dim3 gv(BB * VV / GBM, HH / GBN);   // (32, 8)
    gemm_nt_split_kernel<<<gq, 256>>>(query, Wq, bq, (float*)qp);
    gemm_nt_split_kernel<<<gv, 256>>>(values, Wv, bv, (float*)vp);

    // K3: fused tanh-scores + softmax + context (pipelined)
    cudaFuncSetAttribute(attn_kernel, cudaFuncAttributeMaxDynamicSharedMemorySize, SMEM_BYTES);
    attn_kernel<<<BB * (QQ / QT), 512, SMEM_BYTES>>>(
        (const float*)qp, (const float*)vp, values, mask, wc, bc, out_ctx, out_w);
}

// round 6
// speedup vs baseline: 1.1430x; 1.0321x over previous
#include <cuda_runtime.h>
#include <cuda_bf16.h>
#include <cstdint>

// ---------------------------------------------------------------------------
// Problem sizes (fixed)
// ---------------------------------------------------------------------------
#define BB 8
#define QQ 128
#define VV 512
#define HH 512

#define NQ (BB*QQ*HH)
#define NV (BB*VV*HH)

// ---------------------------------------------------------------------------
// Device scratch (no allocations allowed)
// ---------------------------------------------------------------------------
__device__ float g_qp[NQ];
__device__ float g_vp[NV];

// ---------------------------------------------------------------------------
// Fast transcendentals
// ---------------------------------------------------------------------------
__device__ __forceinline__ float fast_ex2(float x) {
    float y;
    asm("ex2.approx.ftz.f32 %0, %1;" : "=f"(y) : "f"(x));
    return y;
}
__device__ __forceinline__ float tanh_fast(float x) {
    float y;
    asm("tanh.approx.f32 %0, %1;" : "=f"(y) : "f"(x));
    return y;
}

// cp.async helpers
__device__ __forceinline__ void cp_async16(float* dst_smem, const float* src_gmem) {
    uint32_t d = (uint32_t)__cvta_generic_to_shared(dst_smem);
    asm volatile("cp.async.cg.shared.global [%0], [%1], 16;\n" :: "r"(d), "l"(src_gmem) : "memory");
}
__device__ __forceinline__ void cp_commit() {
    asm volatile("cp.async.commit_group;\n" ::: "memory");
}
__device__ __forceinline__ void cp_wait1() {
    asm volatile("cp.async.wait_group 1;\n" ::: "memory");
}
__device__ __forceinline__ void cp_wait0() {
    asm volatile("cp.async.wait_group 0;\n" ::: "memory");
}

// ---------------------------------------------------------------------------
// K2: merged projection GEMM. One launch does BOTH qp and vp.
// C[m][n] = sum_k A[m][k]*B[n][k] + bias[n]  (NT, 3x bf16 split, fp32 acc)
// grid.x = 40 M-tiles (first 8 -> qp from query/Wq, rest 32 -> vp from
// values/Wv); grid.y = 8 N-tiles. Register-prefetch pipeline: LDG for
// k-block t+1 issue right after staging t, and drain under the MMA loop.
// ---------------------------------------------------------------------------
#define GBM 128
#define GBN 64
#define GBK 32
#define QP_MTILES (BB*QQ/GBM)   // 8
#define VP_MTILES (BB*VV/GBM)   // 32

__device__ __forceinline__ void mma16816(float* d, const uint32_t* a, const uint32_t* b) {
    asm volatile(
        "mma.sync.aligned.m16n8k16.row.col.f32.bf16.bf16.f32 "
        "{%0,%1,%2,%3}, {%4,%5,%6,%7}, {%8,%9}, {%0,%1,%2,%3};"
        : "+f"(d[0]), "+f"(d[1]), "+f"(d[2]), "+f"(d[3])
        : "r"(a[0]), "r"(a[1]), "r"(a[2]), "r"(a[3]), "r"(b[0]), "r"(b[1]));
}

// split a float4 into 4 hi bf16 (8B) and 4 lo bf16 (8B)
__device__ __forceinline__ void split4(float4 v, uint2* hi, uint2* lo) {
    __nv_bfloat16 h0 = __float2bfloat16(v.x);
    __nv_bfloat16 h1 = __float2bfloat16(v.y);
    __nv_bfloat16 h2 = __float2bfloat16(v.z);
    __nv_bfloat16 h3 = __float2bfloat16(v.w);
    __nv_bfloat16 l0 = __float2bfloat16(v.x - __bfloat162float(h0));
    __nv_bfloat16 l1 = __float2bfloat16(v.y - __bfloat162float(h1));
    __nv_bfloat16 l2 = __float2bfloat16(v.z - __bfloat162float(h2));
    __nv_bfloat16 l3 = __float2bfloat16(v.w - __bfloat162float(h3));
    __nv_bfloat162 hA = {h0, h1}, hB = {h2, h3};
    __nv_bfloat162 lA = {l0, l1}, lB = {l2, l3};
    hi->x = *(uint32_t*)&hA; hi->y = *(uint32_t*)&hB;
    lo->x = *(uint32_t*)&lA; lo->y = *(uint32_t*)&lB;
}

__global__ __launch_bounds__(256, 2) void gemm_both_kernel(
    const float* __restrict__ query, const float* __restrict__ Wq,
    const float* __restrict__ bq,
    const float* __restrict__ values, const float* __restrict__ Wv,
    const float* __restrict__ bv) {
    const int K = HH;
    const int N = HH;
    __shared__ __align__(16) __nv_bfloat16 As[2][GBM][GBK + 8];
    __shared__ __align__(16) __nv_bfloat16 Bs[2][GBN][GBK + 8];

    const float *A, *B, *bias;
    float* C;
    int mt = blockIdx.x;
    if (mt < QP_MTILES) {
        A = query; B = Wq; bias = bq; C = g_qp;
    } else {
        mt -= QP_MTILES;
        A = values; B = Wv; bias = bv; C = g_vp;
    }
    const int m0 = mt * GBM;
    const int n0 = blockIdx.y * GBN;
    const int tid = threadIdx.x;
    const int wid = tid >> 5;
    const int lane = tid & 31;
    const int wm = (wid >> 1) * 32;
    const int wn = (wid & 1) * 32;
    const int gp = lane >> 2;
    const int tg = lane & 3;

    // per-thread staging coordinates
    int ar[4], ac[4];
#pragma unroll
    for (int i = 0; i < 4; i++) {
        int linear = i * 256 + tid;
        ar[i] = linear >> 3;           // row 0..127
        ac[i] = (linear & 7) * 4;      // col offset 0..28
    }
    int br[2], bcc[2];
#pragma unroll
    for (int i = 0; i < 2; i++) {
        int linear = i * 256 + tid;
        br[i] = linear >> 3;           // row 0..63
        bcc[i] = (linear & 7) * 4;
    }

    float d[2][4][4];
#pragma unroll
    for (int mi = 0; mi < 2; mi++)
#pragma unroll
        for (int ni = 0; ni < 4; ni++)
#pragma unroll
            for (int r = 0; r < 4; r++) d[mi][ni][r] = 0.0f;

    // prologue: load k-block 0 into registers
    float4 aReg[4], bReg[2];
#pragma unroll
    for (int i = 0; i < 4; i++)
        aReg[i] = *(const float4*)(A + (size_t)(m0 + ar[i]) * K + ac[i]);
#pragma unroll
    for (int i = 0; i < 2; i++)
        bReg[i] = *(const float4*)(B + (size_t)(n0 + br[i]) * K + bcc[i]);

    for (int k0 = 0; k0 < K; k0 += GBK) {
        // stage registers -> smem (split to hi/lo)
#pragma unroll
        for (int i = 0; i < 4; i++) {
            uint2 hi, lo;
            split4(aReg[i], &hi, &lo);
            *(uint2*)(&As[0][ar[i]][ac[i]]) = hi;
            *(uint2*)(&As[1][ar[i]][ac[i]]) = lo;
        }
#pragma unroll
        for (int i = 0; i < 2; i++) {
            uint2 hi, lo;
            split4(bReg[i], &hi, &lo);
            *(uint2*)(&Bs[0][br[i]][bcc[i]]) = hi;
            *(uint2*)(&Bs[1][br[i]][bcc[i]]) = lo;
        }
        __syncthreads();

        // issue LDGs for next k-block; they drain under the MMA loop
        if (k0 + GBK < K) {
            int kn = k0 + GBK;
#pragma unroll
            for (int i = 0; i < 4; i++)
                aReg[i] = *(const float4*)(A + (size_t)(m0 + ar[i]) * K + kn + ac[i]);
#pragma unroll
            for (int i = 0; i < 2; i++)
                bReg[i] = *(const float4*)(B + (size_t)(n0 + br[i]) * K + kn + bcc[i]);
        }

#pragma unroll
        for (int ks = 0; ks < GBK; ks += 16) {
            uint32_t a[2][2][4];
            uint32_t bf[2][4][2];
#pragma unroll
            for (int s = 0; s < 2; s++) {
#pragma unroll
                for (int mi = 0; mi < 2; mi++) {
                    int row = wm + mi * 16;
                    a[s][mi][0] = *(const uint32_t*)&As[s][row + gp][ks + tg * 2];
                    a[s][mi][1] = *(const uint32_t*)&As[s][row + gp + 8][ks + tg * 2];
                    a[s][mi][2] = *(const uint32_t*)&As[s][row + gp][ks + tg * 2 + 8];
                    a[s][mi][3] = *(const uint32_t*)&As[s][row + gp + 8][ks + tg * 2 + 8];
                }
#pragma unroll
                for (int ni = 0; ni < 4; ni++) {
                    int col = wn + ni * 8;
                    bf[s][ni][0] = *(const uint32_t*)&Bs[s][col + gp][ks + tg * 2];
                    bf[s][ni][1] = *(const uint32_t*)&Bs[s][col + gp][ks + tg * 2 + 8];
                }
            }
#pragma unroll
            for (int mi = 0; mi < 2; mi++)
#pragma unroll
                for (int ni = 0; ni < 4; ni++) {
                    mma16816(d[mi][ni], a[0][mi], bf[0][ni]);  // hi*hi
                    mma16816(d[mi][ni], a[0][mi], bf[1][ni]);  // hi*lo
                    mma16816(d[mi][ni], a[1][mi], bf[0][ni]);  // lo*hi
                }
        }
        __syncthreads();
    }

#pragma unroll
    for (int mi = 0; mi < 2; mi++)
#pragma unroll
        for (int ni = 0; ni < 4; ni++) {
            int r = m0 + wm + mi * 16 + gp;
            int c = n0 + wn + ni * 8 + tg * 2;
            float b0 = bias[c], b1 = bias[c + 1];
            float* Cp = C + (size_t)r * N + c;
            float2 v0 = make_float2(d[mi][ni][0] + b0, d[mi][ni][1] + b1);
            float2 v1 = make_float2(d[mi][ni][2] + b0, d[mi][ni][3] + b1);
            *(float2*)(Cp) = v0;
            *(float2*)(Cp + 8 * N) = v1;
        }
}

// ---------------------------------------------------------------------------
// K3: fused scores(tanh) + softmax + context, cp.async double-buffered tiles.
// (unchanged from Round 5 — isolating the GEMM delta)
// ---------------------------------------------------------------------------
#define QT 8
#define VT 32
#define NTILE (VV/VT)   // 16
#define HP (HH + 4)     // 516 floats; 129 16B slots == 1 mod 8
#define VP (VV + 8)

#define SMEM_FLOATS (QT*HP + HH + QT*VP + 16 + VV + 2*VT*HP)
#define SMEM_BYTES (SMEM_FLOATS * 4)

__device__ __forceinline__ void load_tile_async(float* dst, const float* src, int tid) {
#pragma unroll
    for (int i = 0; i < (VT * 128) / 512; i++) {
        int linear = i * 512 + tid;
        int r = linear >> 7;
        int c = (linear & 127) << 2;
        cp_async16(dst + r * HP + c, src + r * HH + c);
    }
}

__global__ __launch_bounds__(512, 1) void attn_kernel(
    const float* __restrict__ qp, const float* __restrict__ vp,
    const float* __restrict__ values, const int* __restrict__ mask,
    const float* __restrict__ wc, const float* __restrict__ bc,
    float* __restrict__ out_ctx, float* __restrict__ out_w) {
    extern __shared__ float sm[];
    float* qp_s = sm;                    // QT*HP
    float* wc_s = qp_s + QT * HP;        // HH
    float* sc   = wc_s + HH;             // QT*VP
    float* wsum = sc + QT * VP;          // 16
    int* mask_s = (int*)(wsum + 16);     // VV
    float* buf  = (float*)(mask_s + VV); // 2 * VT*HP

    const int tid = threadIdx.x;
    const int b = blockIdx.x >> 4;
    const int qt = blockIdx.x & 15;
    const int q0 = qt * QT;

    const float* vpb = vp + (size_t)b * VV * HH;
    const float* valb = values + (size_t)b * VV * HH;

    // prefetch score tile 0
    load_tile_async(buf, vpb, tid);
    cp_commit();

    // load qp tile, wc, mask (regular loads, overlapped with the cp.async)
    for (int i = tid; i < QT * (HH / 4); i += 512) {
        int r = i / (HH / 4), c = i % (HH / 4);
        ((float4*)(qp_s + r * HP))[c] =
            ((const float4*)(qp + (size_t)(b * QQ + q0 + r) * HH))[c];
    }
    for (int i = tid; i < HH; i += 512) wc_s[i] = wc[i];
    for (int i = tid; i < VV; i += 512) mask_s[i] = mask[b * VV + i];
    const float bcv = bc[0];

    const int q = tid >> 6;          // 0..7
    const int vg = (tid >> 3) & 7;   // 0..7 -> rows vg*4 .. vg*4+3
    const int hc = tid & 7;          // 0..7 interleaved H chunks

    // ---- score phase (double-buffered) ----
    for (int t = 0; t < NTILE; t++) {
        float* cur = buf + (t & 1) * VT * HP;
        if (t + 1 < NTILE) {
            load_tile_async(buf + ((t + 1) & 1) * VT * HP, vpb + (size_t)(t + 1) * VT * HH, tid);
            cp_commit();
            cp_wait1();
        } else {
            cp_wait0();
        }
        __syncthreads();

        const float* qrow = qp_s + q * HP;
        const float* wrow = wc_s;
        const float* v0p = cur + (vg * 4 + 0) * HP;
        const float* v1p = cur + (vg * 4 + 1) * HP;
        const float* v2p = cur + (vg * 4 + 2) * HP;
        const float* v3p = cur + (vg * 4 + 3) * HP;
        float acc0 = 0.f, acc1 = 0.f, acc2 = 0.f, acc3 = 0.f;
#pragma unroll
        for (int i = 0; i < 16; i++) {
            int h = i * 32 + hc * 4;
            float4 a = *(const float4*)(qrow + h);
            float4 w = *(const float4*)(wrow + h);
            float4 c0 = *(const float4*)(v0p + h);
            float4 c1 = *(const float4*)(v1p + h);
            float4 c2 = *(const float4*)(v2p + h);
            float4 c3 = *(const float4*)(v3p + h);
            acc0 = fmaf(w.x, tanh_fast(a.x + c0.x), acc0);
            acc0 = fmaf(w.y, tanh_fast(a.y + c0.y), acc0);
            acc0 = fmaf(w.z, tanh_fast(a.z + c0.z), acc0);
            acc0 = fmaf(w.w, tanh_fast(a.w + c0.w), acc0);
            acc1 = fmaf(w.x, tanh_fast(a.x + c1.x), acc1);
            acc1 = fmaf(w.y, tanh_fast(a.y + c1.y), acc1);
            acc1 = fmaf(w.z, tanh_fast(a.z + c1.z), acc1);
            acc1 = fmaf(w.w, tanh_fast(a.w + c1.w), acc1);
            acc2 = fmaf(w.x, tanh_fast(a.x + c2.x), acc2);
            acc2 = fmaf(w.y, tanh_fast(a.y + c2.y), acc2);
            acc2 = fmaf(w.z, tanh_fast(a.z + c2.z), acc2);
            acc2 = fmaf(w.w, tanh_fast(a.w + c2.w), acc2);
            acc3 = fmaf(w.x, tanh_fast(a.x + c3.x), acc3);
            acc3 = fmaf(w.y, tanh_fast(a.y + c3.y), acc3);
            acc3 = fmaf(w.z, tanh_fast(a.z + c3.z), acc3);
            acc3 = fmaf(w.w, tanh_fast(a.w + c3.w), acc3);
        }
        acc0 += __shfl_xor_sync(0xffffffffu, acc0, 1);
        acc0 += __shfl_xor_sync(0xffffffffu, acc0, 2);
        acc0 += __shfl_xor_sync(0xffffffffu, acc0, 4);
        acc1 += __shfl_xor_sync(0xffffffffu, acc1, 1);
        acc1 += __shfl_xor_sync(0xffffffffu, acc1, 2);
        acc1 += __shfl_xor_sync(0xffffffffu, acc1, 4);
        acc2 += __shfl_xor_sync(0xffffffffu, acc2, 1);
        acc2 += __shfl_xor_sync(0xffffffffu, acc2, 2);
        acc2 += __shfl_xor_sync(0xffffffffu, acc2, 4);
        acc3 += __shfl_xor_sync(0xffffffffu, acc3, 1);
        acc3 += __shfl_xor_sync(0xffffffffu, acc3, 2);
        acc3 += __shfl_xor_sync(0xffffffffu, acc3, 4);
        if (hc < 4) {
            float myacc = (hc == 0) ? acc0 : (hc == 1) ? acc1 : (hc == 2) ? acc2 : acc3;
            int v = t * VT + vg * 4 + hc;
            float p = mask_s[v] ? fast_ex2((myacc + bcv) * 1.4426950408889634f) : 0.0f;
            sc[q * VP + v] = p;
        }
        __syncthreads();
    }

    // prefetch first values tile while doing softmax
    load_tile_async(buf, valb, tid);
    cp_commit();

    // ---- deterministic row sums ----
    const int vl = tid & 63;
    {
        float s = 0.0f;
#pragma unroll
        for (int j = 0; j < 8; j++) s += sc[q * VP + vl + 64 * j];
#pragma unroll
        for (int off = 16; off; off >>= 1) s += __shfl_down_sync(0xffffffffu, s, off);
        if ((tid & 31) == 0) wsum[tid >> 5] = s;
    }
    __syncthreads();
    const float inv = 1.0f / (wsum[2 * q] + wsum[2 * q + 1]);

    {
        float* outw_row = out_w + (size_t)(b * QQ + q0 + q) * VV;
#pragma unroll
        for (int j = 0; j < 8; j++) {
            int v = vl + 64 * j;
            float w = sc[q * VP + v] * inv;
            sc[q * VP + v] = w;
            outw_row[v] = w;
        }
    }

    // ---- context phase (double-buffered) ----
    const int hq = tid & 127;
    const int qg = tid >> 7;
    float4 acc0 = make_float4(0.f, 0.f, 0.f, 0.f);
    float4 acc1 = make_float4(0.f, 0.f, 0.f, 0.f);

    for (int t = 0; t < NTILE; t++) {
        float* cur = buf + (t & 1) * VT * HP;
        if (t + 1 < NTILE) {
            load_tile_async(buf + ((t + 1) & 1) * VT * HP, valb + (size_t)(t + 1) * VT * HH, tid);
            cp_commit();
            cp_wait1();
        } else {
            cp_wait0();
        }
        __syncthreads();

        const float* w0 = sc + (2 * qg) * VP + t * VT;
        const float* w1 = sc + (2 * qg + 1) * VP + t * VT;
#pragma unroll 4
        for (int v = 0; v < VT; v += 2) {
            float2 a0 = *(const float2*)(w0 + v);
            float2 a1 = *(const float2*)(w1 + v);
            float4 c0 = ((const float4*)(cur + v * HP))[hq];
            float4 c1 = ((const float4*)(cur + (v + 1) * HP))[hq];
            acc0.x += a0.x * c0.x + a0.y * c1.x;
            acc0.y += a0.x * c0.y + a0.y * c1.y;
            acc0.z += a0.x * c0.z + a0.y * c1.z;
            acc0.w += a0.x * c0.w + a0.y * c1.w;
            acc1.x += a1.x * c0.x + a1.y * c1.x;
            acc1.y += a1.x * c0.y + a1.y * c1.y;
            acc1.z += a1.x * c0.z + a1.y * c1.z;
            acc1.w += a1.x * c0.w + a1.y * c1.w;
        }
        __syncthreads();
    }
    float* oc0 = out_ctx + (size_t)(b * QQ + q0 + 2 * qg) * HH;
    ((float4*)oc0)[hq] = acc0;
    ((float4*)(oc0 + HH))[hq] = acc1;
}

// ---------------------------------------------------------------------------
// Launch
// ---------------------------------------------------------------------------
extern "C" void kernel_launch(void* const* d_in, const int* in_sizes, int n_in,
                              void* d_out, int out_size) {
    const float* query  = (const float*)d_in[0];
    const float* values = (const float*)d_in[1];
    const int*   mask   = (const int*)d_in[2];
    const float* Wq     = (const float*)d_in[3];
    const float* bq     = (const float*)d_in[4];
    const float* Wv     = (const float*)d_in[5];
    const float* bv     = (const float*)d_in[6];
    const float* wc     = (const float*)d_in[7];
    const float* bc     = (const float*)d_in[8];

    float* out_ctx = (float*)d_out;
    float* out_w   = (float*)d_out + (size_t)BB * QQ * HH;

    void *qp, *vp;
    cudaGetSymbolAddress(&qp, g_qp);
    cudaGetSymbolAddress(&vp, g_vp);

    // K2: both projections in ONE launch (40 M-tiles x 8 N-tiles = 320 blocks)
    dim3 gboth(QP_MTILES + VP_MTILES, HH / GBN);
    gemm_both_kernel<<<gboth, 256>>>(query, Wq, bq, values, Wv, bv);

    // K3: fused tanh-scores + softmax + context (pipelined)
    cudaFuncSetAttribute(attn_kernel, cudaFuncAttributeMaxDynamicSharedMemorySize, SMEM_BYTES);
    attn_kernel<<<BB * (QQ / QT), 512, SMEM_BYTES>>>(
        (const float*)qp, (const float*)vp, values, mask, wc, bc, out_ctx, out_w);
}

// round 7
// speedup vs baseline: 1.2507x; 1.0943x over previous
#include <cuda_runtime.h>
#include <cuda_bf16.h>
#include <cstdint>

// ---------------------------------------------------------------------------
// Problem sizes (fixed)
// ---------------------------------------------------------------------------
#define BB 8
#define QQ 128
#define VV 512
#define HH 512

#define NQ (BB*QQ*HH)
#define NV (BB*VV*HH)

// ---------------------------------------------------------------------------
// Device scratch (no allocations allowed)
// ---------------------------------------------------------------------------
__device__ float g_qp[NQ];
__device__ float g_vp[NV];

// ---------------------------------------------------------------------------
// Fast transcendentals
// ---------------------------------------------------------------------------
__device__ __forceinline__ float fast_ex2(float x) {
    float y;
    asm("ex2.approx.ftz.f32 %0, %1;" : "=f"(y) : "f"(x));
    return y;
}
__device__ __forceinline__ float tanh_fast(float x) {
    float y;
    asm("tanh.approx.f32 %0, %1;" : "=f"(y) : "f"(x));
    return y;
}

// cp.async helpers
__device__ __forceinline__ void cp_async16(float* dst_smem, const float* src_gmem) {
    uint32_t d = (uint32_t)__cvta_generic_to_shared(dst_smem);
    asm volatile("cp.async.cg.shared.global [%0], [%1], 16;\n" :: "r"(d), "l"(src_gmem) : "memory");
}
__device__ __forceinline__ void cp_commit() {
    asm volatile("cp.async.commit_group;\n" ::: "memory");
}
__device__ __forceinline__ void cp_wait1() {
    asm volatile("cp.async.wait_group 1;\n" ::: "memory");
}
__device__ __forceinline__ void cp_wait0() {
    asm volatile("cp.async.wait_group 0;\n" ::: "memory");
}

// ---------------------------------------------------------------------------
// K2: merged projection GEMM (qp + vp in one launch), GBK=64.
// C[m][n] = sum_k A[m][k]*B[n][k] + bias[n]  (NT, 3x bf16 split, fp32 acc)
// Register prefetch of k-block t+1 drains under the MMA loop of block t.
// ---------------------------------------------------------------------------
#define GBM 128
#define GBN 64
#define GBK 64
#define GSTRIDE (GBK + 8)   // bf16 elements per row
#define QP_MTILES (BB*QQ/GBM)   // 8
#define VP_MTILES (BB*VV/GBM)   // 32

#define GEMM_SMEM_BF16 (2*GBM*GSTRIDE + 2*GBN*GSTRIDE)
#define GEMM_SMEM_BYTES (GEMM_SMEM_BF16 * 2)

__device__ __forceinline__ void mma16816(float* d, const uint32_t* a, const uint32_t* b) {
    asm volatile(
        "mma.sync.aligned.m16n8k16.row.col.f32.bf16.bf16.f32 "
        "{%0,%1,%2,%3}, {%4,%5,%6,%7}, {%8,%9}, {%0,%1,%2,%3};"
        : "+f"(d[0]), "+f"(d[1]), "+f"(d[2]), "+f"(d[3])
        : "r"(a[0]), "r"(a[1]), "r"(a[2]), "r"(a[3]), "r"(b[0]), "r"(b[1]));
}

// split a float4 into 4 hi bf16 (8B) and 4 lo bf16 (8B)
__device__ __forceinline__ void split4(float4 v, uint2* hi, uint2* lo) {
    __nv_bfloat16 h0 = __float2bfloat16(v.x);
    __nv_bfloat16 h1 = __float2bfloat16(v.y);
    __nv_bfloat16 h2 = __float2bfloat16(v.z);
    __nv_bfloat16 h3 = __float2bfloat16(v.w);
    __nv_bfloat16 l0 = __float2bfloat16(v.x - __bfloat162float(h0));
    __nv_bfloat16 l1 = __float2bfloat16(v.y - __bfloat162float(h1));
    __nv_bfloat16 l2 = __float2bfloat16(v.z - __bfloat162float(h2));
    __nv_bfloat16 l3 = __float2bfloat16(v.w - __bfloat162float(h3));
    __nv_bfloat162 hA = {h0, h1}, hB = {h2, h3};
    __nv_bfloat162 lA = {l0, l1}, lB = {l2, l3};
    hi->x = *(uint32_t*)&hA; hi->y = *(uint32_t*)&hB;
    lo->x = *(uint32_t*)&lA; lo->y = *(uint32_t*)&lB;
}

__global__ __launch_bounds__(256, 2) void gemm_both_kernel(
    const float* __restrict__ query, const float* __restrict__ Wq,
    const float* __restrict__ bq,
    const float* __restrict__ values, const float* __restrict__ Wv,
    const float* __restrict__ bv) {
    const int K = HH;
    const int N = HH;
    extern __shared__ __nv_bfloat16 gsm[];
    __nv_bfloat16* As = gsm;                       // [2][GBM][GSTRIDE]
    __nv_bfloat16* Bs = gsm + 2 * GBM * GSTRIDE;   // [2][GBN][GSTRIDE]

    const float *A, *B, *bias;
    float* C;
    int mt = blockIdx.x;
    if (mt < QP_MTILES) {
        A = query; B = Wq; bias = bq; C = g_qp;
    } else {
        mt -= QP_MTILES;
        A = values; B = Wv; bias = bv; C = g_vp;
    }
    const int m0 = mt * GBM;
    const int n0 = blockIdx.y * GBN;
    const int tid = threadIdx.x;
    const int wid = tid >> 5;
    const int lane = tid & 31;
    const int wm = (wid >> 1) * 32;
    const int wn = (wid & 1) * 32;
    const int gp = lane >> 2;
    const int tg = lane & 3;

    // staging coords: A 128x64 fp32 = 2048 float4, 8/thread; B 64x64 = 1024, 4/thread
    const int sr = tid >> 4;            // base row selector
    const int scc = (tid & 15) * 4;     // element col 0..60

    float d[2][4][4];
#pragma unroll
    for (int mi = 0; mi < 2; mi++)
#pragma unroll
        for (int ni = 0; ni < 4; ni++)
#pragma unroll
            for (int r = 0; r < 4; r++) d[mi][ni][r] = 0.0f;

    float4 aReg[8], bReg[4];
#pragma unroll
    for (int i = 0; i < 8; i++)
        aReg[i] = *(const float4*)(A + (size_t)(m0 + i * 16 + sr) * K + scc);
#pragma unroll
    for (int i = 0; i < 4; i++)
        bReg[i] = *(const float4*)(B + (size_t)(n0 + i * 16 + sr) * K + scc);

    for (int k0 = 0; k0 < K; k0 += GBK) {
        // stage registers -> smem (split to hi/lo)
#pragma unroll
        for (int i = 0; i < 8; i++) {
            uint2 hi, lo;
            split4(aReg[i], &hi, &lo);
            int r = i * 16 + sr;
            *(uint2*)(As + r * GSTRIDE + scc) = hi;
            *(uint2*)(As + GBM * GSTRIDE + r * GSTRIDE + scc) = lo;
        }
#pragma unroll
        for (int i = 0; i < 4; i++) {
            uint2 hi, lo;
            split4(bReg[i], &hi, &lo);
            int r = i * 16 + sr;
            *(uint2*)(Bs + r * GSTRIDE + scc) = hi;
            *(uint2*)(Bs + GBN * GSTRIDE + r * GSTRIDE + scc) = lo;
        }
        __syncthreads();

        // issue LDGs for next k-block; they drain under the MMA loop
        if (k0 + GBK < K) {
            int kn = k0 + GBK;
#pragma unroll
            for (int i = 0; i < 8; i++)
                aReg[i] = *(const float4*)(A + (size_t)(m0 + i * 16 + sr) * K + kn + scc);
#pragma unroll
            for (int i = 0; i < 4; i++)
                bReg[i] = *(const float4*)(B + (size_t)(n0 + i * 16 + sr) * K + kn + scc);
        }

#pragma unroll
        for (int ks = 0; ks < GBK; ks += 16) {
            uint32_t a[2][2][4];
            uint32_t bf[2][4][2];
#pragma unroll
            for (int s = 0; s < 2; s++) {
                const __nv_bfloat16* Ab = As + s * GBM * GSTRIDE;
                const __nv_bfloat16* Bb = Bs + s * GBN * GSTRIDE;
#pragma unroll
                for (int mi = 0; mi < 2; mi++) {
                    int row = wm + mi * 16;
                    a[s][mi][0] = *(const uint32_t*)(Ab + (row + gp) * GSTRIDE + ks + tg * 2);
                    a[s][mi][1] = *(const uint32_t*)(Ab + (row + gp + 8) * GSTRIDE + ks + tg * 2);
                    a[s][mi][2] = *(const uint32_t*)(Ab + (row + gp) * GSTRIDE + ks + tg * 2 + 8);
                    a[s][mi][3] = *(const uint32_t*)(Ab + (row + gp + 8) * GSTRIDE + ks + tg * 2 + 8);
                }
#pragma unroll
                for (int ni = 0; ni < 4; ni++) {
                    int col = wn + ni * 8;
                    bf[s][ni][0] = *(const uint32_t*)(Bb + (col + gp) * GSTRIDE + ks + tg * 2);
                    bf[s][ni][1] = *(const uint32_t*)(Bb + (col + gp) * GSTRIDE + ks + tg * 2 + 8);
                }
            }
#pragma unroll
            for (int mi = 0; mi < 2; mi++)
#pragma unroll
                for (int ni = 0; ni < 4; ni++) {
                    mma16816(d[mi][ni], a[0][mi], bf[0][ni]);  // hi*hi
                    mma16816(d[mi][ni], a[0][mi], bf[1][ni]);  // hi*lo
                    mma16816(d[mi][ni], a[1][mi], bf[0][ni]);  // lo*hi
                }
        }
        __syncthreads();
    }

#pragma unroll
    for (int mi = 0; mi < 2; mi++)
#pragma unroll
        for (int ni = 0; ni < 4; ni++) {
            int r = m0 + wm + mi * 16 + gp;
            int c = n0 + wn + ni * 8 + tg * 2;
            float b0 = bias[c], b1 = bias[c + 1];
            float* Cp = C + (size_t)r * N + c;
            float2 v0 = make_float2(d[mi][ni][0] + b0, d[mi][ni][1] + b1);
            float2 v1 = make_float2(d[mi][ni][2] + b0, d[mi][ni][3] + b1);
            *(float2*)(Cp) = v0;
            *(float2*)(Cp + 8 * N) = v1;
        }
}

// ---------------------------------------------------------------------------
// K3: fused scores(tanh) + softmax + context, cp.async double-buffered tiles.
// Score phase unchanged from R6. Context phase: v-split mapping —
// thread = col(128) x qg(2: q0-3/q4-7) x vhalf(2); 4 queries per thread over
// half the v-rows -> tile LDS read amplification 2x (was 4x); deterministic
// smem combine of the two v-halves at the end (reuses qp_s).
// ---------------------------------------------------------------------------
#define QT 8
#define VT 32
#define NTILE (VV/VT)   // 16
#define HP (HH + 4)     // 516 floats; 129 16B slots == 1 mod 8
#define VP (VV + 8)

#define SMEM_FLOATS (QT*HP + HH + QT*VP + 16 + VV + 2*VT*HP)
#define SMEM_BYTES (SMEM_FLOATS * 4)

__device__ __forceinline__ void load_tile_async(float* dst, const float* src, int tid) {
#pragma unroll
    for (int i = 0; i < (VT * 128) / 512; i++) {
        int linear = i * 512 + tid;
        int r = linear >> 7;
        int c = (linear & 127) << 2;
        cp_async16(dst + r * HP + c, src + r * HH + c);
    }
}

__global__ __launch_bounds__(512, 1) void attn_kernel(
    const float* __restrict__ qp, const float* __restrict__ vp,
    const float* __restrict__ values, const int* __restrict__ mask,
    const float* __restrict__ wc, const float* __restrict__ bc,
    float* __restrict__ out_ctx, float* __restrict__ out_w) {
    extern __shared__ float sm[];
    float* qp_s = sm;                    // QT*HP (reused as combine buffer)
    float* wc_s = qp_s + QT * HP;        // HH
    float* sc   = wc_s + HH;             // QT*VP
    float* wsum = sc + QT * VP;          // 16
    int* mask_s = (int*)(wsum + 16);     // VV
    float* buf  = (float*)(mask_s + VV); // 2 * VT*HP

    const int tid = threadIdx.x;
    const int b = blockIdx.x >> 4;
    const int qt = blockIdx.x & 15;
    const int q0 = qt * QT;

    const float* vpb = vp + (size_t)b * VV * HH;
    const float* valb = values + (size_t)b * VV * HH;

    // prefetch score tile 0
    load_tile_async(buf, vpb, tid);
    cp_commit();

    // load qp tile, wc, mask
    for (int i = tid; i < QT * (HH / 4); i += 512) {
        int r = i / (HH / 4), c = i % (HH / 4);
        ((float4*)(qp_s + r * HP))[c] =
            ((const float4*)(qp + (size_t)(b * QQ + q0 + r) * HH))[c];
    }
    for (int i = tid; i < HH; i += 512) wc_s[i] = wc[i];
    for (int i = tid; i < VV; i += 512) mask_s[i] = mask[b * VV + i];
    const float bcv = bc[0];

    const int q = tid >> 6;          // 0..7
    const int vg = (tid >> 3) & 7;   // 0..7 -> rows vg*4 .. vg*4+3
    const int hc = tid & 7;          // 0..7 interleaved H chunks

    // ---- score phase (double-buffered) ----
    for (int t = 0; t < NTILE; t++) {
        float* cur = buf + (t & 1) * VT * HP;
        if (t + 1 < NTILE) {
            load_tile_async(buf + ((t + 1) & 1) * VT * HP, vpb + (size_t)(t + 1) * VT * HH, tid);
            cp_commit();
            cp_wait1();
        } else {
            cp_wait0();
        }
        __syncthreads();

        const float* qrow = qp_s + q * HP;
        const float* wrow = wc_s;
        const float* v0p = cur + (vg * 4 + 0) * HP;
        const float* v1p = cur + (vg * 4 + 1) * HP;
        const float* v2p = cur + (vg * 4 + 2) * HP;
        const float* v3p = cur + (vg * 4 + 3) * HP;
        float acc0 = 0.f, acc1 = 0.f, acc2 = 0.f, acc3 = 0.f;
#pragma unroll
        for (int i = 0; i < 16; i++) {
            int h = i * 32 + hc * 4;
            float4 a = *(const float4*)(qrow + h);
            float4 w = *(const float4*)(wrow + h);
            float4 c0 = *(const float4*)(v0p + h);
            float4 c1 = *(const float4*)(v1p + h);
            float4 c2 = *(const float4*)(v2p + h);
            float4 c3 = *(const float4*)(v3p + h);
            acc0 = fmaf(w.x, tanh_fast(a.x + c0.x), acc0);
            acc0 = fmaf(w.y, tanh_fast(a.y + c0.y), acc0);
            acc0 = fmaf(w.z, tanh_fast(a.z + c0.z), acc0);
            acc0 = fmaf(w.w, tanh_fast(a.w + c0.w), acc0);
            acc1 = fmaf(w.x, tanh_fast(a.x + c1.x), acc1);
            acc1 = fmaf(w.y, tanh_fast(a.y + c1.y), acc1);
            acc1 = fmaf(w.z, tanh_fast(a.z + c1.z), acc1);
            acc1 = fmaf(w.w, tanh_fast(a.w + c1.w), acc1);
            acc2 = fmaf(w.x, tanh_fast(a.x + c2.x), acc2);
            acc2 = fmaf(w.y, tanh_fast(a.y + c2.y), acc2);
            acc2 = fmaf(w.z, tanh_fast(a.z + c2.z), acc2);
            acc2 = fmaf(w.w, tanh_fast(a.w + c2.w), acc2);
            acc3 = fmaf(w.x, tanh_fast(a.x + c3.x), acc3);
            acc3 = fmaf(w.y, tanh_fast(a.y + c3.y), acc3);
            acc3 = fmaf(w.z, tanh_fast(a.z + c3.z), acc3);
            acc3 = fmaf(w.w, tanh_fast(a.w + c3.w), acc3);
        }
        acc0 += __shfl_xor_sync(0xffffffffu, acc0, 1);
        acc0 += __shfl_xor_sync(0xffffffffu, acc0, 2);
        acc0 += __shfl_xor_sync(0xffffffffu, acc0, 4);
        acc1 += __shfl_xor_sync(0xffffffffu, acc1, 1);
        acc1 += __shfl_xor_sync(0xffffffffu, acc1, 2);
        acc1 += __shfl_xor_sync(0xffffffffu, acc1, 4);
        acc2 += __shfl_xor_sync(0xffffffffu, acc2, 1);
        acc2 += __shfl_xor_sync(0xffffffffu, acc2, 2);
        acc2 += __shfl_xor_sync(0xffffffffu, acc2, 4);
        acc3 += __shfl_xor_sync(0xffffffffu, acc3, 1);
        acc3 += __shfl_xor_sync(0xffffffffu, acc3, 2);
        acc3 += __shfl_xor_sync(0xffffffffu, acc3, 4);
        if (hc < 4) {
            float myacc = (hc == 0) ? acc0 : (hc == 1) ? acc1 : (hc == 2) ? acc2 : acc3;
            int v = t * VT + vg * 4 + hc;
            float p = mask_s[v] ? fast_ex2((myacc + bcv) * 1.4426950408889634f) : 0.0f;
            sc[q * VP + v] = p;
        }
        __syncthreads();
    }

    // prefetch first values tile while doing softmax
    load_tile_async(buf, valb, tid);
    cp_commit();

    // ---- deterministic row sums ----
    const int vl = tid & 63;
    {
        float s = 0.0f;
#pragma unroll
        for (int j = 0; j < 8; j++) s += sc[q * VP + vl + 64 * j];
#pragma unroll
        for (int off = 16; off; off >>= 1) s += __shfl_down_sync(0xffffffffu, s, off);
        if ((tid & 31) == 0) wsum[tid >> 5] = s;
    }
    __syncthreads();
    const float inv = 1.0f / (wsum[2 * q] + wsum[2 * q + 1]);

    {
        float* outw_row = out_w + (size_t)(b * QQ + q0 + q) * VV;
#pragma unroll
        for (int j = 0; j < 8; j++) {
            int v = vl + 64 * j;
            float w = sc[q * VP + v] * inv;
            sc[q * VP + v] = w;
            outw_row[v] = w;
        }
    }

    // ---- context phase (v-split, double-buffered) ----
    const int ccol = tid & 127;         // float4 column 0..127
    const int cqg  = (tid >> 7) & 1;    // 0: q0-3, 1: q4-7
    const int cvh  = tid >> 8;          // v-half within each tile
    float4 ca0 = make_float4(0.f,0.f,0.f,0.f);
    float4 ca1 = make_float4(0.f,0.f,0.f,0.f);
    float4 ca2 = make_float4(0.f,0.f,0.f,0.f);
    float4 ca3 = make_float4(0.f,0.f,0.f,0.f);

    for (int t = 0; t < NTILE; t++) {
        float* cur = buf + (t & 1) * VT * HP;
        if (t + 1 < NTILE) {
            load_tile_async(buf + ((t + 1) & 1) * VT * HP, valb + (size_t)(t + 1) * VT * HH, tid);
            cp_commit();
            cp_wait1();
        } else {
            cp_wait0();
        }
        __syncthreads();

        const float* wq0 = sc + (cqg * 4 + 0) * VP + t * VT + cvh * 16;
        const float* wq1 = sc + (cqg * 4 + 1) * VP + t * VT + cvh * 16;
        const float* wq2 = sc + (cqg * 4 + 2) * VP + t * VT + cvh * 16;
        const float* wq3 = sc + (cqg * 4 + 3) * VP + t * VT + cvh * 16;
        const float* cb = cur + cvh * 16 * HP;
#pragma unroll
        for (int v = 0; v < 16; v++) {
            float4 c = ((const float4*)(cb + v * HP))[ccol];
            float w0 = wq0[v], w1 = wq1[v], w2 = wq2[v], w3 = wq3[v];
            ca0.x = fmaf(w0, c.x, ca0.x); ca0.y = fmaf(w0, c.y, ca0.y);
            ca0.z = fmaf(w0, c.z, ca0.z); ca0.w = fmaf(w0, c.w, ca0.w);
            ca1.x = fmaf(w1, c.x, ca1.x); ca1.y = fmaf(w1, c.y, ca1.y);
            ca1.z = fmaf(w1, c.z, ca1.z); ca1.w = fmaf(w1, c.w, ca1.w);
            ca2.x = fmaf(w2, c.x, ca2.x); ca2.y = fmaf(w2, c.y, ca2.y);
            ca2.z = fmaf(w2, c.z, ca2.z); ca2.w = fmaf(w2, c.w, ca2.w);
            ca3.x = fmaf(w3, c.x, ca3.x); ca3.y = fmaf(w3, c.y, ca3.y);
            ca3.z = fmaf(w3, c.z, ca3.z); ca3.w = fmaf(w3, c.w, ca3.w);
        }
        __syncthreads();
    }

    // combine the two v-halves (deterministic: vh0 + vh1) and write out
    float4* xb = (float4*)qp_s;   // qp_s is dead now; 1032 float4 >= 1024
    const int xi = (cqg * 128 + ccol) * 4;
    if (cvh == 1) {
        xb[xi + 0] = ca0; xb[xi + 1] = ca1; xb[xi + 2] = ca2; xb[xi + 3] = ca3;
    }
    __syncthreads();
    if (cvh == 0) {
        float4 p0 = xb[xi + 0], p1 = xb[xi + 1], p2 = xb[xi + 2], p3 = xb[xi + 3];
        ca0.x += p0.x; ca0.y += p0.y; ca0.z += p0.z; ca0.w += p0.w;
        ca1.x += p1.x; ca1.y += p1.y; ca1.z += p1.z; ca1.w += p1.w;
        ca2.x += p2.x; ca2.y += p2.y; ca2.z += p2.z; ca2.w += p2.w;
        ca3.x += p3.x; ca3.y += p3.y; ca3.z += p3.z; ca3.w += p3.w;
        float* oc = out_ctx + (size_t)(b * QQ + q0 + cqg * 4) * HH;
        ((float4*)(oc + 0 * HH))[ccol] = ca0;
        ((float4*)(oc + 1 * HH))[ccol] = ca1;
        ((float4*)(oc + 2 * HH))[ccol] = ca2;
        ((float4*)(oc + 3 * HH))[ccol] = ca3;
    }
}

// ---------------------------------------------------------------------------
// Launch
// ---------------------------------------------------------------------------
extern "C" void kernel_launch(void* const* d_in, const int* in_sizes, int n_in,
                              void* d_out, int out_size) {
    const float* query  = (const float*)d_in[0];
    const float* values = (const float*)d_in[1];
    const int*   mask   = (const int*)d_in[2];
    const float* Wq     = (const float*)d_in[3];
    const float* bq     = (const float*)d_in[4];
    const float* Wv     = (const float*)d_in[5];
    const float* bv     = (const float*)d_in[6];
    const float* wc     = (const float*)d_in[7];
    const float* bc     = (const float*)d_in[8];

    float* out_ctx = (float*)d_out;
    float* out_w   = (float*)d_out + (size_t)BB * QQ * HH;

    void *qp, *vp;
    cudaGetSymbolAddress(&qp, g_qp);
    cudaGetSymbolAddress(&vp, g_vp);

    // K2: both projections in ONE launch, GBK=64 (dynamic smem)
    cudaFuncSetAttribute(gemm_both_kernel, cudaFuncAttributeMaxDynamicSharedMemorySize, GEMM_SMEM_BYTES);
    dim3 gboth(QP_MTILES + VP_MTILES, HH / GBN);
    gemm_both_kernel<<<gboth, 256, GEMM_SMEM_BYTES>>>(query, Wq, bq, values, Wv, bv);

    // K3: fused tanh-scores + softmax + context (pipelined)
    cudaFuncSetAttribute(attn_kernel, cudaFuncAttributeMaxDynamicSharedMemorySize, SMEM_BYTES);
    attn_kernel<<<BB * (QQ / QT), 512, SMEM_BYTES>>>(
        (const float*)qp, (const float*)vp, values, mask, wc, bc, out_ctx, out_w);
}